// round 16
// baseline (speedup 1.0000x reference)
#include <cuda_runtime.h>
#include <cuda_bf16.h>
#include <cstdint>

// Problem constants
#define B_DIM 16
#define P_DIM 87
#define K_DIM 4
#define N_DIM 32768
#define D_MODEL 256
#define HIDDEN 128
#define LOGIT_SCALE 0.125f   // ATTN_SCALE / TAU

// Output layout (flattened tuple, fp32)
#define OUT_PROBS 0
#define OUT_LOGITS 1392
#define OUT_COORDS 2784

// Scratch (no allocations allowed -> __device__ globals; zero-initialized,
// re-zeroed by the last attn block each launch for graph-replay safety)
__device__ float g_q[64 * D_MODEL];              // final projected queries
__device__ float g_acc[B_DIM * K_DIM * 4];       // per (b,k): sumw, sx, sy, sz
__device__ int   g_done_rg[16];                  // per-row-group qproj counters
__device__ int   g_attn_done = 0;                // attn block completion counter

#define QP_BLOCKS 128       // 16 row-groups x 8 i-chunks (32 i's each)
#define ATTN_BLOCKS 2048    // 128 x-tiles * 16 batches
#define HH_BLOCKS 348       // human-head blocks, 4 rows each
#define ATTN_BASE QP_BLOCKS                 // 128
#define HH_BASE (QP_BLOCKS + ATTN_BLOCKS)   // 2176

// Attn: each block covers 256 rows; warp w owns rows [w*32, w*32+32),
// processed 4 at a time through a warp-private double-buffered pipeline.
#define WROWS 4              // rows per warp-buffer
#define NTW 8                // iterations per warp (32 rows)
// smem: 8 warps * 2 * 4KB buffers (64KB) + 8*24 xyz floats + 32 float4 red
#define SMEM_BYTES 66816

// ---------------------------------------------------------------------------
// cp.async + packed-f32x2 helpers
// ---------------------------------------------------------------------------
__device__ __forceinline__ void cp16(void* dst, const void* src) {
    uint32_t d = (uint32_t)__cvta_generic_to_shared(dst);
    asm volatile("cp.async.cg.shared.global [%0], [%1], 16;" :: "r"(d), "l"(src));
}
__device__ __forceinline__ void cp4(void* dst, const void* src) {
    uint32_t d = (uint32_t)__cvta_generic_to_shared(dst);
    asm volatile("cp.async.ca.shared.global [%0], [%1], 4;" :: "r"(d), "l"(src));
}
__device__ __forceinline__ void cp_commit() {
    asm volatile("cp.async.commit_group;");
}
__device__ __forceinline__ int ld_acquire(const int* p) {
    int v;
    asm volatile("ld.acquire.gpu.global.b32 %0, [%1];" : "=r"(v) : "l"(p));
    return v;
}
__device__ __forceinline__ uint64_t pk2(float lo, float hi) {
    uint64_t r;
    asm("mov.b64 %0, {%1, %2};" : "=l"(r) : "f"(lo), "f"(hi));
    return r;
}
__device__ __forceinline__ uint64_t mul2(uint64_t a, uint64_t b) {
    uint64_t d;
    asm("mul.rn.f32x2 %0, %1, %2;" : "=l"(d) : "l"(a), "l"(b));
    return d;
}
__device__ __forceinline__ uint64_t fma2(uint64_t a, uint64_t b, uint64_t c) {
    uint64_t d;
    asm("fma.rn.f32x2 %0, %1, %2, %3;" : "=l"(d) : "l"(a), "l"(b), "l"(c));
    return d;
}
__device__ __forceinline__ float hsum2(uint64_t v) {
    float lo, hi;
    asm("mov.b64 {%0, %1}, %2;" : "=f"(lo), "=f"(hi) : "l"(v));
    return lo + hi;
}

// ---------------------------------------------------------------------------
// Single fused kernel:
//   [0, 128):       q projection chunks -> atomicAdd g_q, release g_done_rg
//   [128, 2176):    attention pooling (warp-private pipelines; per-batch spin)
//   [2176, 2524):   human MLP head
// ---------------------------------------------------------------------------
__global__ void __launch_bounds__(256, 3)
fused_kernel(const float* __restrict__ feats,
             const float* __restrict__ xyz,
             const float* __restrict__ hq,
             const float* __restrict__ oq,
             const float* __restrict__ W1,
             const float* __restrict__ b1,
             const float* __restrict__ W2,
             const float* __restrict__ b2,
             const float* __restrict__ Wq,
             const float* __restrict__ bq,
             float* __restrict__ out) {
    extern __shared__ float sm[];
    const int t = threadIdx.x;
    const int warp = t >> 5;
    const int lane = t & 31;

    if (blockIdx.x < QP_BLOCKS) {
        // ========== q projection chunk: 4 rows x 32-wide i-chunk ==========
        float* xs = sm;                                        // 128 floats
        float4* part4 = reinterpret_cast<float4*>(sm + 128);   // 32 KB
        const int rg = blockIdx.x >> 3;      // row group 0..15
        const int c = blockIdx.x & 7;        // i-chunk 0..7 (32 i's each)

        if (t < 128) {
            const int r = t >> 5;
            const int idx = t & 31;
            xs[r * 32 + idx] = oq[(size_t)(rg * 4 + r) * D_MODEL + c * 32 + idx];
        }
        __syncthreads();

        const float4* wqv = reinterpret_cast<const float4*>(Wq);
        float4 aA[4], aB[4];
#pragma unroll
        for (int r = 0; r < 4; r++) { aA[r] = {0,0,0,0}; aB[r] = {0,0,0,0}; }
#pragma unroll
        for (int ii = 0; ii < 4; ii++) {
            const int il = warp * 4 + ii;          // 0..31 within chunk
            const int ig = c * 32 + il;            // global i
            const float4 wa = wqv[ig * 64 + lane];
            const float4 wb = wqv[ig * 64 + 32 + lane];
            const float x0 = xs[il];
            const float x1 = xs[32 + il];
            const float x2 = xs[64 + il];
            const float x3 = xs[96 + il];
            aA[0].x = fmaf(x0, wa.x, aA[0].x); aA[0].y = fmaf(x0, wa.y, aA[0].y);
            aA[0].z = fmaf(x0, wa.z, aA[0].z); aA[0].w = fmaf(x0, wa.w, aA[0].w);
            aB[0].x = fmaf(x0, wb.x, aB[0].x); aB[0].y = fmaf(x0, wb.y, aB[0].y);
            aB[0].z = fmaf(x0, wb.z, aB[0].z); aB[0].w = fmaf(x0, wb.w, aB[0].w);
            aA[1].x = fmaf(x1, wa.x, aA[1].x); aA[1].y = fmaf(x1, wa.y, aA[1].y);
            aA[1].z = fmaf(x1, wa.z, aA[1].z); aA[1].w = fmaf(x1, wa.w, aA[1].w);
            aB[1].x = fmaf(x1, wb.x, aB[1].x); aB[1].y = fmaf(x1, wb.y, aB[1].y);
            aB[1].z = fmaf(x1, wb.z, aB[1].z); aB[1].w = fmaf(x1, wb.w, aB[1].w);
            aA[2].x = fmaf(x2, wa.x, aA[2].x); aA[2].y = fmaf(x2, wa.y, aA[2].y);
            aA[2].z = fmaf(x2, wa.z, aA[2].z); aA[2].w = fmaf(x2, wa.w, aA[2].w);
            aB[2].x = fmaf(x2, wb.x, aB[2].x); aB[2].y = fmaf(x2, wb.y, aB[2].y);
            aB[2].z = fmaf(x2, wb.z, aB[2].z); aB[2].w = fmaf(x2, wb.w, aB[2].w);
            aA[3].x = fmaf(x3, wa.x, aA[3].x); aA[3].y = fmaf(x3, wa.y, aA[3].y);
            aA[3].z = fmaf(x3, wa.z, aA[3].z); aA[3].w = fmaf(x3, wa.w, aA[3].w);
            aB[3].x = fmaf(x3, wb.x, aB[3].x); aB[3].y = fmaf(x3, wb.y, aB[3].y);
            aB[3].z = fmaf(x3, wb.z, aB[3].z); aB[3].w = fmaf(x3, wb.w, aB[3].w);
        }
#pragma unroll
        for (int r = 0; r < 4; r++) {
            part4[(warp * 4 + r) * 64 + lane] = aA[r];
            part4[(warp * 4 + r) * 64 + 32 + lane] = aB[r];
        }
        __syncthreads();

        {
            const int r = t >> 6;
            const int cc = t & 63;
            float4 s = part4[r * 64 + cc];
#pragma unroll
            for (int j = 1; j < 8; j++) {
                const float4 p = part4[(j * 4 + r) * 64 + cc];
                s.x += p.x; s.y += p.y; s.z += p.z; s.w += p.w;
            }
            if (c == 0) {
                const float4 bb = reinterpret_cast<const float4*>(bq)[cc];
                s.x += bb.x; s.y += bb.y; s.z += bb.z; s.w += bb.w;
            }
            float* dst = g_q + (size_t)(rg * 4 + r) * D_MODEL + cc * 4;
            atomicAdd(dst + 0, s.x);
            atomicAdd(dst + 1, s.y);
            atomicAdd(dst + 2, s.z);
            atomicAdd(dst + 3, s.w);
        }
        __syncthreads();
        if (t == 0) {
            __threadfence();
            atomicAdd(&g_done_rg[rg], 1);
        }
        return;
    }

    if (blockIdx.x >= HH_BASE) {
        // ================= human head: 4 rows per block =================
        const int blk = blockIdx.x - HH_BASE;
        float* xs = sm;
        float4* part4 = reinterpret_cast<float4*>(sm + 1024);

        const float* src = hq + (size_t)blk * 4 * D_MODEL;
#pragma unroll
        for (int j = 0; j < 4; j++) xs[t + j * 256] = src[t + j * 256];
        __syncthreads();

        const int i0 = warp * 32;
        const float4* w1v = reinterpret_cast<const float4*>(W1);
        float4 a0 = {0,0,0,0}, a1 = {0,0,0,0}, a2 = {0,0,0,0}, a3 = {0,0,0,0};
#pragma unroll 4
        for (int ii = 0; ii < 32; ii++) {
            const int i = i0 + ii;
            const float4 wv = w1v[i * 32 + lane];
            const float x0 = xs[i];
            const float x1 = xs[256 + i];
            const float x2 = xs[512 + i];
            const float x3 = xs[768 + i];
            a0.x = fmaf(x0, wv.x, a0.x); a0.y = fmaf(x0, wv.y, a0.y);
            a0.z = fmaf(x0, wv.z, a0.z); a0.w = fmaf(x0, wv.w, a0.w);
            a1.x = fmaf(x1, wv.x, a1.x); a1.y = fmaf(x1, wv.y, a1.y);
            a1.z = fmaf(x1, wv.z, a1.z); a1.w = fmaf(x1, wv.w, a1.w);
            a2.x = fmaf(x2, wv.x, a2.x); a2.y = fmaf(x2, wv.y, a2.y);
            a2.z = fmaf(x2, wv.z, a2.z); a2.w = fmaf(x2, wv.w, a2.w);
            a3.x = fmaf(x3, wv.x, a3.x); a3.y = fmaf(x3, wv.y, a3.y);
            a3.z = fmaf(x3, wv.z, a3.z); a3.w = fmaf(x3, wv.w, a3.w);
        }
        part4[(warp * 4 + 0) * 32 + lane] = a0;
        part4[(warp * 4 + 1) * 32 + lane] = a1;
        part4[(warp * 4 + 2) * 32 + lane] = a2;
        part4[(warp * 4 + 3) * 32 + lane] = a3;
        __syncthreads();

        if (t < 128) {
            const int r = t >> 5;
            const int l = t & 31;
            float4 s = part4[r * 32 + l];
#pragma unroll
            for (int j = 1; j < 8; j++) {
                const float4 p = part4[(j * 4 + r) * 32 + l];
                s.x += p.x; s.y += p.y; s.z += p.z; s.w += p.w;
            }
            const float4 bb = reinterpret_cast<const float4*>(b1)[l];
            s.x = fmaxf(s.x + bb.x, 0.0f);
            s.y = fmaxf(s.y + bb.y, 0.0f);
            s.z = fmaxf(s.z + bb.z, 0.0f);
            s.w = fmaxf(s.w + bb.w, 0.0f);
            const float4 w2 = reinterpret_cast<const float4*>(W2)[l];
            float v = s.x * w2.x + s.y * w2.y + s.z * w2.z + s.w * w2.w;
#pragma unroll
            for (int off = 16; off > 0; off >>= 1)
                v += __shfl_xor_sync(0xffffffffu, v, off);
            if (l == 0) {
                const int row = blk * 4 + r;
                const float logit = v + b2[0];
                out[OUT_LOGITS + row] = logit;
                out[OUT_PROBS + row] = 1.0f / (1.0f + __expf(-logit));
            }
        }
        return;
    }

    // ================= attention pooling (warp-decoupled) =================
    const int abx = blockIdx.x - ATTN_BASE;   // 0..2047
    const int b = abx >> 7;                   // batch 0..15
    const int xt = abx & 127;                 // x-tile 0..127
    const int row0 = xt * 256 + warp * 32;    // this warp's first row

    // warp-private smem: 2 x 4-row (4KB) buffers + 2 x 12 xyz floats
    float* wbuf = sm + warp * 2048;                 // 8 KB per warp
    float* wxyz = sm + 16384 + warp * 24;
    float4* red4 = reinterpret_cast<float4*>(sm + 16384 + 192);
    __shared__ int is_last;

    const float* fbase = feats + ((size_t)b * N_DIM + row0) * D_MODEL;
    const float* xbase = xyz + ((size_t)b * N_DIM + row0) * 3;

    // prologue FIRST (independent of g_q): issue buffers 0 and 1
#pragma unroll
    for (int pt = 0; pt < 2; pt++) {
        const float* src = fbase + pt * WROWS * 256;
        float* dst = wbuf + pt * 1024;
#pragma unroll
        for (int j = 0; j < 8; j++) {
            const int f = (lane + j * 32) * 4;
            cp16(dst + f, src + f);
        }
        if (lane < WROWS * 3)
            cp4(wxyz + pt * 12 + lane, xbase + pt * WROWS * 3 + lane);
        cp_commit();
    }

    // acquire-spin until THIS batch's 8 qproj chunk blocks are done
    if (t == 0) {
        while (ld_acquire(&g_done_rg[b]) < 8)
            __nanosleep(32);
    }
    __syncthreads();   // the only block barrier before the epilogue

    // q in registers, packed as f32x2 pairs: qp[k][0..3] covers the 16 elems
    // this lane owns of query k (elems 4*lane..4*lane+3 and 128+4*lane..+3).
    uint64_t qp[K_DIM][4];
    {
        const float4* q4 =
            reinterpret_cast<const float4*>(g_q + (size_t)b * K_DIM * D_MODEL);
#pragma unroll
        for (int k = 0; k < K_DIM; k++) {
            const float4 qa = q4[k * 64 + lane];
            const float4 qb = q4[k * 64 + 32 + lane];
            qp[k][0] = pk2(qa.x, qa.y);
            qp[k][1] = pk2(qa.z, qa.w);
            qp[k][2] = pk2(qb.x, qb.y);
            qp[k][3] = pk2(qb.z, qb.w);
        }
    }

    float aw = 0.0f, ax = 0.0f, ay = 0.0f, az = 0.0f;
    const int myrow = (lane >> 2) & 3;   // lanes<16: which row this lane owns

#pragma unroll 1
    for (int it = 0; it < NTW; it++) {
        if (it < NTW - 1) asm volatile("cp.async.wait_group 1;");
        else              asm volatile("cp.async.wait_group 0;");
        __syncwarp();

        const int bi = it & 1;
        const float4* B4 = reinterpret_cast<const float4*>(wbuf + bi * 1024);
        const float* XZ = wxyz + bi * 12;

        float keep = 0.0f;
#pragma unroll
        for (int rb = 0; rb < WROWS; rb++) {
            const float4 fa = B4[rb * 64 + lane];
            const float4 fb = B4[rb * 64 + 32 + lane];
            const uint64_t a0 = pk2(fa.x, fa.y);
            const uint64_t a1 = pk2(fa.z, fa.w);
            const uint64_t b0 = pk2(fb.x, fb.y);
            const uint64_t b1p = pk2(fb.z, fb.w);

            // packed dot: 4 f32x2 ops per query instead of 8 scalar FMAs
            uint64_t c0 = mul2(a0, qp[0][0]);
            uint64_t c1 = mul2(a0, qp[1][0]);
            uint64_t c2 = mul2(a0, qp[2][0]);
            uint64_t c3 = mul2(a0, qp[3][0]);
            c0 = fma2(a1, qp[0][1], c0);
            c1 = fma2(a1, qp[1][1], c1);
            c2 = fma2(a1, qp[2][1], c2);
            c3 = fma2(a1, qp[3][1], c3);
            c0 = fma2(b0, qp[0][2], c0);
            c1 = fma2(b0, qp[1][2], c1);
            c2 = fma2(b0, qp[2][2], c2);
            c3 = fma2(b0, qp[3][2], c3);
            c0 = fma2(b1p, qp[0][3], c0);
            c1 = fma2(b1p, qp[1][3], c1);
            c2 = fma2(b1p, qp[2][3], c2);
            c3 = fma2(b1p, qp[3][3], c3);
            float p0 = hsum2(c0);
            float p1 = hsum2(c1);
            float p2 = hsum2(c2);
            float p3 = hsum2(c3);

            // Quad transpose-reduce: every lane ends with sum for k = lane&3
            float t1 = (lane & 1) ? p0 : p1;
            t1 = __shfl_xor_sync(0xffffffffu, t1, 1);
            float t2 = (lane & 1) ? p2 : p3;
            t2 = __shfl_xor_sync(0xffffffffu, t2, 1);
            const float aab = ((lane & 1) ? p1 : p0) + t1;
            const float ccd = ((lane & 1) ? p3 : p2) + t2;
            float t3 = (lane & 2) ? aab : ccd;
            t3 = __shfl_xor_sync(0xffffffffu, t3, 2);
            float v = ((lane & 2) ? ccd : aab) + t3;
            v += __shfl_xor_sync(0xffffffffu, v, 4);
            v += __shfl_xor_sync(0xffffffffu, v, 8);
            v += __shfl_xor_sync(0xffffffffu, v, 16);
            if (myrow == rb) keep = v;
        }

        const float wgt = __expf(keep * LOGIT_SCALE);
        if (lane < 16) {     // lane = 4*myrow + k
            const float px = XZ[myrow * 3 + 0];
            const float py = XZ[myrow * 3 + 1];
            const float pz = XZ[myrow * 3 + 2];
            aw += wgt;
            ax = fmaf(wgt, px, ax);
            ay = fmaf(wgt, py, ay);
            az = fmaf(wgt, pz, az);
        }

        __syncwarp();   // all lanes done reading wbuf[bi] before refill

        if (it + 2 < NTW) {
            const float* src = fbase + (it + 2) * WROWS * 256;
            float* dst = wbuf + bi * 1024;
#pragma unroll
            for (int j = 0; j < 8; j++) {
                const int f = (lane + j * 32) * 4;
                cp16(dst + f, src + f);
            }
            if (lane < WROWS * 3)
                cp4(wxyz + bi * 12 + lane, xbase + (it + 2) * WROWS * 3 + lane);
            cp_commit();
        }
    }

    // fold the 4 row-owners per k (lane bits 2-3), lanes<16 hold data
    aw += __shfl_xor_sync(0xffffffffu, aw, 4);
    ax += __shfl_xor_sync(0xffffffffu, ax, 4);
    ay += __shfl_xor_sync(0xffffffffu, ay, 4);
    az += __shfl_xor_sync(0xffffffffu, az, 4);
    aw += __shfl_xor_sync(0xffffffffu, aw, 8);
    ax += __shfl_xor_sync(0xffffffffu, ax, 8);
    ay += __shfl_xor_sync(0xffffffffu, ay, 8);
    az += __shfl_xor_sync(0xffffffffu, az, 8);
    if (lane < 4)
        red4[warp * 4 + lane] = make_float4(aw, ax, ay, az);
    __syncthreads();

    if (t < 16) {
        const int k = t >> 2;
        const int c = t & 3;
        const float* rf = reinterpret_cast<const float*>(red4);
        float s = 0.0f;
#pragma unroll
        for (int j = 0; j < 8; j++) s += rf[(j * 4 + k) * 4 + c];
        atomicAdd(&g_acc[((size_t)b * K_DIM + k) * 4 + c], s);
    }
    __syncthreads();

    // last attn block finalizes coords and resets state for the next replay
    if (t == 0) {
        __threadfence();
        const int old = atomicAdd(&g_attn_done, 1);
        is_last = (old == ATTN_BLOCKS - 1);
    }
    __syncthreads();
    if (is_last) {
        if (t < B_DIM * K_DIM) {
            volatile float* ga = g_acc + (size_t)t * 4;
            const float sw = ga[0];
            const float sx = ga[1];
            const float sy = ga[2];
            const float sz = ga[3];
            const float inv = 1.0f / sw;
            out[OUT_COORDS + t * 3 + 0] = sx * inv;
            out[OUT_COORDS + t * 3 + 1] = sy * inv;
            out[OUT_COORDS + t * 3 + 2] = sz * inv;
            ga[0] = 0.0f; ga[1] = 0.0f; ga[2] = 0.0f; ga[3] = 0.0f;
        }
        if (t < 16) g_done_rg[t] = 0;
#pragma unroll
        for (int j = 0; j < 64; j++)
            g_q[t + j * 256] = 0.0f;
        __syncthreads();
        if (t == 0) {
            g_attn_done = 0;
            __threadfence();
        }
    }
}

// ---------------------------------------------------------------------------
extern "C" void kernel_launch(void* const* d_in, const int* in_sizes, int n_in,
                              void* d_out, int out_size) {
    const float* hq    = (const float*)d_in[0];
    const float* oq    = (const float*)d_in[1];
    const float* feats = (const float*)d_in[2];
    const float* xyz   = (const float*)d_in[3];
    const float* W1    = (const float*)d_in[4];
    const float* b1    = (const float*)d_in[5];
    const float* W2    = (const float*)d_in[6];
    const float* b2    = (const float*)d_in[7];
    const float* Wq    = (const float*)d_in[8];
    const float* bq    = (const float*)d_in[9];
    float* out = (float*)d_out;

    cudaFuncSetAttribute(fused_kernel,
                         cudaFuncAttributeMaxDynamicSharedMemorySize,
                         SMEM_BYTES);

    fused_kernel<<<QP_BLOCKS + ATTN_BLOCKS + HH_BLOCKS, 256, SMEM_BYTES>>>(
        feats, xyz, hq, oq, W1, b1, W2, b2, Wq, bq, out);
}